// round 5
// baseline (speedup 1.0000x reference)
#include <cuda_runtime.h>
#include <cuda_bf16.h>
#include <cstdint>

#define N_NODES 50000
#define N_EDGES 400000
#define E_TOT   (N_EDGES + N_NODES)
#define G_GRAPHS 256
#define HC 200
#define C_CH 100
#define SLOPE 0.2f

#define TM_TILES 3125          // 50000 / 16 (exact)
#define TN_TILES 25            // 200 / 8 (exact)
#define KS16_MAX 21            // 336 / 16
#define NB_SCAN 196            // ceil(50000/256)

// ---------------- scratch (device globals; no allocation allowed) ------------
__device__ float g_h[(size_t)N_NODES * HC];
__device__ float g_x[(size_t)N_NODES * HC];
__device__ float g_es[N_NODES * 2];
__device__ float g_ed[N_NODES * 2];
__device__ int   g_rowptr[N_NODES + 1];
__device__ int   g_cnt[N_NODES];
__device__ int   g_fill[N_NODES];
__device__ int   g_colsrc[E_TOT];
__device__ float g_pool[G_GRAPHS * HC];
__device__ int   g_bsum[256];
__device__ int   g_boff[256];
// permuted bf16 hi/lo operands in exact mma.m16n8k16 fragment order
__device__ uint4 g_pah[(size_t)TM_TILES * KS16_MAX * 32];
__device__ uint4 g_pal[(size_t)TM_TILES * KS16_MAX * 32];
__device__ uint2 g_pbh[(size_t)TN_TILES * KS16_MAX * 32];
__device__ uint2 g_pbl[(size_t)TN_TILES * KS16_MAX * 32];

// ---------------- CSR build --------------------------------------------------
__global__ void k_init_counts() {
    int i = blockIdx.x * blockDim.x + threadIdx.x;
    if (i < N_NODES) { g_cnt[i] = 1; g_fill[i] = 1; }
}

__global__ void k_count(const int* __restrict__ ei) {
    int e = blockIdx.x * blockDim.x + threadIdx.x;
    if (e < N_EDGES) atomicAdd(&g_cnt[ei[N_EDGES + e]], 1);
}

__global__ void k_scan1() {
    __shared__ int ws[8];
    int b = blockIdx.x, t = threadIdx.x;
    int i = b * 256 + t;
    int lane = t & 31, w = t >> 5;
    int v = (i < N_NODES) ? g_cnt[i] : 0;
    int s = v;
#pragma unroll
    for (int off = 1; off < 32; off <<= 1) {
        int u = __shfl_up_sync(0xffffffffu, s, off);
        if (lane >= off) s += u;
    }
    if (lane == 31) ws[w] = s;
    __syncthreads();
    if (t == 0) {
        int run = 0;
#pragma unroll
        for (int j = 0; j < 8; j++) { int tmp = ws[j]; ws[j] = run; run += tmp; }
        g_bsum[b] = run;
    }
    __syncthreads();
    if (i < N_NODES) g_rowptr[i + 1] = s + ws[w];
}

__global__ void k_scan2() {
    __shared__ int ws[8];
    int t = threadIdx.x;
    int lane = t & 31, w = t >> 5;
    int v = (t < NB_SCAN) ? g_bsum[t] : 0;
    int s = v;
#pragma unroll
    for (int off = 1; off < 32; off <<= 1) {
        int u = __shfl_up_sync(0xffffffffu, s, off);
        if (lane >= off) s += u;
    }
    if (lane == 31) ws[w] = s;
    __syncthreads();
    if (t == 0) {
        int run = 0;
#pragma unroll
        for (int j = 0; j < 8; j++) { int tmp = ws[j]; ws[j] = run; run += tmp; }
    }
    __syncthreads();
    if (t < NB_SCAN) g_boff[t] = s + ws[w] - v;
}

__global__ void k_scan3() {
    int i = blockIdx.x * blockDim.x + threadIdx.x;
    if (i == 0) g_rowptr[0] = 0;
    if (i < N_NODES) g_rowptr[i + 1] += g_boff[i >> 8];
}

__global__ void k_selfloop() {
    int i = blockIdx.x * blockDim.x + threadIdx.x;
    if (i < N_NODES) g_colsrc[g_rowptr[i]] = i;
}

__global__ void k_fill(const int* __restrict__ ei) {
    int e = blockIdx.x * blockDim.x + threadIdx.x;
    if (e < N_EDGES) {
        int d = ei[N_EDGES + e];
        int pos = g_rowptr[d] + atomicAdd(&g_fill[d], 1);
        g_colsrc[pos] = ei[e];
    }
}

__global__ void k_zero_scores() {
    int i = blockIdx.x * blockDim.x + threadIdx.x;
    if (i < N_NODES * 2) { g_es[i] = 0.f; g_ed[i] = 0.f; }
}

// ---------------- bf16 helpers -----------------------------------------------
__device__ __forceinline__ uint32_t packbf(float a, float b) {
    __nv_bfloat162 p = __floats2bfloat162_rn(a, b);
    return *(uint32_t*)&p;
}
__device__ __forceinline__ float bfhi(float v) {
    return __bfloat162float(__float2bfloat16_rn(v));
}

__device__ __forceinline__ void mma_bf16(float& c0, float& c1, float& c2, float& c3,
                                         uint32_t a0, uint32_t a1, uint32_t a2, uint32_t a3,
                                         uint32_t b0, uint32_t b1) {
    asm volatile(
        "mma.sync.aligned.m16n8k16.row.col.f32.bf16.bf16.f32 "
        "{%0,%1,%2,%3},{%4,%5,%6,%7},{%8,%9},{%0,%1,%2,%3};"
        : "+f"(c0), "+f"(c1), "+f"(c2), "+f"(c3)
        : "r"(a0), "r"(a1), "r"(a2), "r"(a3), "r"(b0), "r"(b1));
}

// ---------------- operand pre-permute + hi/lo bf16 split ---------------------
__device__ __forceinline__ void convA_body(const float* __restrict__ A, int K, int KS, int t) {
    int lane = t & 31;
    int rest = t >> 5;
    int ks = rest % KS;
    int tm = rest / KS;
    int groupr = lane >> 2, kc = lane & 3;
    int r0 = tm * 16 + groupr, r1 = r0 + 8;
    int k0 = ks * 16 + kc * 2;
    float v[2][4];
    const float* p0 = A + (size_t)r0 * K;
    const float* p1 = A + (size_t)r1 * K;
#pragma unroll
    for (int j = 0; j < 4; j++) {
        int k = k0 + (j >> 1) * 8 + (j & 1);
        v[0][j] = (k < K) ? p0[k] : 0.f;
        v[1][j] = (k < K) ? p1[k] : 0.f;
    }
    float h[2][4], l[2][4];
#pragma unroll
    for (int r = 0; r < 2; r++)
#pragma unroll
        for (int j = 0; j < 4; j++) { h[r][j] = bfhi(v[r][j]); l[r][j] = v[r][j] - h[r][j]; }
    g_pah[t] = make_uint4(packbf(h[0][0], h[0][1]), packbf(h[1][0], h[1][1]),
                          packbf(h[0][2], h[0][3]), packbf(h[1][2], h[1][3]));
    g_pal[t] = make_uint4(packbf(l[0][0], l[0][1]), packbf(l[1][0], l[1][1]),
                          packbf(l[0][2], l[0][3]), packbf(l[1][2], l[1][3]));
}

__global__ void k_convA(const float* __restrict__ A, int K, int KS, int total) {
    int t = blockIdx.x * blockDim.x + threadIdx.x;
    if (t < total) convA_body(A, K, KS, t);
}
__global__ void k_convA_gx(int K, int KS, int total) {
    int t = blockIdx.x * blockDim.x + threadIdx.x;
    if (t < total) convA_body(g_x, K, KS, t);
}

__global__ void k_convB(const float* __restrict__ B, int K, int KS, int total) {
    int t = blockIdx.x * blockDim.x + threadIdx.x;
    if (t >= total) return;
    int lane = t & 31;
    int rest = t >> 5;
    int ks = rest % KS;
    int tn = rest / KS;
    int groupr = lane >> 2, kc = lane & 3;
    int n = tn * 8 + groupr;
    int k0 = ks * 16 + kc * 2;
    float v[4];
#pragma unroll
    for (int j = 0; j < 4; j++) {
        int k = k0 + (j >> 1) * 8 + (j & 1);
        v[j] = (k < K) ? B[(size_t)k * HC + n] : 0.f;
    }
    float h[4], l[4];
#pragma unroll
    for (int j = 0; j < 4; j++) { h[j] = bfhi(v[j]); l[j] = v[j] - h[j]; }
    g_pbh[t] = make_uint2(packbf(h[0], h[1]), packbf(h[2], h[3]));
    g_pbl[t] = make_uint2(packbf(l[0], l[1]), packbf(l[2], l[3]));
}

// ---------------- smem-free bf16x3 tensor-core GEMM + fused scores ----------
// block = 8 warps (2m x 4n), block tile 64m x 128n. grid = (2, 782).
__global__ void __launch_bounds__(256)
k_gemm_tc(int KS, const float* __restrict__ a_s, const float* __restrict__ a_d) {
    int tid = threadIdx.x;
    int lane = tid & 31, warp = tid >> 5;
    int wm = warp & 1, wn = warp >> 1;
    int tm0 = blockIdx.y * 4 + wm * 2;
    int tnB = blockIdx.x * 16 + wn * 4;
    if (tnB >= TN_TILES) return;

    bool mv0 = tm0 < TM_TILES;
    bool mv1 = (tm0 + 1) < TM_TILES;
    bool nv[4];
#pragma unroll
    for (int ni = 0; ni < 4; ni++) nv[ni] = (tnB + ni) < TN_TILES;

    size_t aBase0 = ((size_t)tm0 * KS) * 32 + lane;
    size_t aBase1 = aBase0 + (size_t)KS * 32;
    size_t bBase[4];
#pragma unroll
    for (int ni = 0; ni < 4; ni++) bBase[ni] = ((size_t)(tnB + ni) * KS) * 32 + lane;

    float acc[2][4][4];
#pragma unroll
    for (int mi = 0; mi < 2; mi++)
#pragma unroll
        for (int ni = 0; ni < 4; ni++)
#pragma unroll
            for (int r = 0; r < 4; r++) acc[mi][ni][r] = 0.f;

    const uint4 z4 = make_uint4(0, 0, 0, 0);
    const uint2 z2 = make_uint2(0, 0);

#pragma unroll 2
    for (int ks = 0; ks < KS; ks++) {
        size_t off = (size_t)ks * 32;
        uint4 ah0 = mv0 ? g_pah[aBase0 + off] : z4;
        uint4 al0 = mv0 ? g_pal[aBase0 + off] : z4;
        uint4 ah1 = mv1 ? g_pah[aBase1 + off] : z4;
        uint4 al1 = mv1 ? g_pal[aBase1 + off] : z4;
        uint2 bh[4], bl[4];
#pragma unroll
        for (int ni = 0; ni < 4; ni++) {
            bh[ni] = nv[ni] ? g_pbh[bBase[ni] + off] : z2;
            bl[ni] = nv[ni] ? g_pbl[bBase[ni] + off] : z2;
        }
#pragma unroll
        for (int ni = 0; ni < 4; ni++) {
            {
                float* c = acc[0][ni];
                mma_bf16(c[0], c[1], c[2], c[3], ah0.x, ah0.y, ah0.z, ah0.w, bh[ni].x, bh[ni].y);
                mma_bf16(c[0], c[1], c[2], c[3], al0.x, al0.y, al0.z, al0.w, bh[ni].x, bh[ni].y);
                mma_bf16(c[0], c[1], c[2], c[3], ah0.x, ah0.y, ah0.z, ah0.w, bl[ni].x, bl[ni].y);
            }
            {
                float* c = acc[1][ni];
                mma_bf16(c[0], c[1], c[2], c[3], ah1.x, ah1.y, ah1.z, ah1.w, bh[ni].x, bh[ni].y);
                mma_bf16(c[0], c[1], c[2], c[3], al1.x, al1.y, al1.z, al1.w, bh[ni].x, bh[ni].y);
                mma_bf16(c[0], c[1], c[2], c[3], ah1.x, ah1.y, ah1.z, ah1.w, bl[ni].x, bl[ni].y);
            }
        }
    }

    int groupr = lane >> 2, kc = lane & 3;

    // sc[mi][rowhalf][{es_h0, es_h1, ed_h0, ed_h1}]
    float sc[2][2][4];
#pragma unroll
    for (int mi = 0; mi < 2; mi++)
#pragma unroll
        for (int rh = 0; rh < 2; rh++)
#pragma unroll
            for (int j = 0; j < 4; j++) sc[mi][rh][j] = 0.f;

#pragma unroll
    for (int mi = 0; mi < 2; mi++) {
        if (!(mi ? mv1 : mv0)) continue;
        int r = (tm0 + mi) * 16 + groupr;
#pragma unroll
        for (int ni = 0; ni < 4; ni++) {
            if (!nv[ni]) continue;
            int c = (tnB + ni) * 8 + kc * 2;
            float as0 = a_s[c], as1 = a_s[c + 1];
            float ad0 = a_d[c], ad1 = a_d[c + 1];
            int hh = (c >= C_CH) ? 1 : 0;        // pair never straddles head boundary
            // store h
            g_h[(size_t)r * HC + c]           = acc[mi][ni][0];
            g_h[(size_t)r * HC + c + 1]       = acc[mi][ni][1];
            g_h[(size_t)(r + 8) * HC + c]     = acc[mi][ni][2];
            g_h[(size_t)(r + 8) * HC + c + 1] = acc[mi][ni][3];
            // partial scores
            sc[mi][0][hh]     += acc[mi][ni][0] * as0 + acc[mi][ni][1] * as1;
            sc[mi][0][2 + hh] += acc[mi][ni][0] * ad0 + acc[mi][ni][1] * ad1;
            sc[mi][1][hh]     += acc[mi][ni][2] * as0 + acc[mi][ni][3] * as1;
            sc[mi][1][2 + hh] += acc[mi][ni][2] * ad0 + acc[mi][ni][3] * ad1;
        }
    }

    // reduce across the 4-lane kc group (lanes groupr*4 .. +3)
#pragma unroll
    for (int mi = 0; mi < 2; mi++)
#pragma unroll
        for (int rh = 0; rh < 2; rh++)
#pragma unroll
            for (int j = 0; j < 4; j++) {
                float v = sc[mi][rh][j];
                v += __shfl_xor_sync(0xffffffffu, v, 1);
                v += __shfl_xor_sync(0xffffffffu, v, 2);
                sc[mi][rh][j] = v;
            }

    if (kc == 0) {
#pragma unroll
        for (int mi = 0; mi < 2; mi++) {
            if (!(mi ? mv1 : mv0)) continue;
#pragma unroll
            for (int rh = 0; rh < 2; rh++) {
                int r = (tm0 + mi) * 16 + groupr + rh * 8;
                atomicAdd(&g_es[r * 2 + 0], sc[mi][rh][0]);
                atomicAdd(&g_es[r * 2 + 1], sc[mi][rh][1]);
                atomicAdd(&g_ed[r * 2 + 0], sc[mi][rh][2]);
                atomicAdd(&g_ed[r * 2 + 1], sc[mi][rh][3]);
            }
        }
    }
}

__device__ __forceinline__ float lrelu(float v) { return v >= 0.f ? v : SLOPE * v; }

// ---------------- warp-per-dst softmax + aggregate + bias + relu -------------
__global__ void k_aggregate(const float* __restrict__ bias) {
    int n = (blockIdx.x * blockDim.x + threadIdx.x) >> 5;
    int lane = threadIdx.x & 31;
    if (n >= N_NODES) return;
    int beg = g_rowptr[n], end = g_rowptr[n + 1];
    float ed0 = g_ed[n * 2 + 0], ed1 = g_ed[n * 2 + 1];

    float m0 = -1e30f, m1 = -1e30f;
    for (int i = beg + lane; i < end; i += 32) {
        int s = g_colsrc[i];
        m0 = fmaxf(m0, lrelu(g_es[s * 2 + 0] + ed0));
        m1 = fmaxf(m1, lrelu(g_es[s * 2 + 1] + ed1));
    }
#pragma unroll
    for (int off = 16; off; off >>= 1) {
        m0 = fmaxf(m0, __shfl_xor_sync(0xffffffffu, m0, off));
        m1 = fmaxf(m1, __shfl_xor_sync(0xffffffffu, m1, off));
    }

    float s0 = 0.f, s1 = 0.f;
    for (int i = beg + lane; i < end; i += 32) {
        int s = g_colsrc[i];
        s0 += __expf(lrelu(g_es[s * 2 + 0] + ed0) - m0);
        s1 += __expf(lrelu(g_es[s * 2 + 1] + ed1) - m1);
    }
#pragma unroll
    for (int off = 16; off; off >>= 1) {
        s0 += __shfl_xor_sync(0xffffffffu, s0, off);
        s1 += __shfl_xor_sync(0xffffffffu, s1, off);
    }
    float inv0 = 1.f / (s0 + 1e-16f), inv1 = 1.f / (s1 + 1e-16f);

    float acc[7];
#pragma unroll
    for (int k = 0; k < 7; k++) acc[k] = 0.f;

    for (int i = beg; i < end; i++) {
        int s = g_colsrc[i];
        float a0 = __expf(lrelu(g_es[s * 2 + 0] + ed0) - m0) * inv0;
        float a1 = __expf(lrelu(g_es[s * 2 + 1] + ed1) - m1) * inv1;
        const float* hr = g_h + (size_t)s * HC;
#pragma unroll
        for (int k = 0; k < 7; k++) {
            int c = lane + 32 * k;
            if (c < HC) acc[k] += (c < C_CH ? a0 : a1) * hr[c];
        }
    }
#pragma unroll
    for (int k = 0; k < 7; k++) {
        int c = lane + 32 * k;
        if (c < HC) {
            float v = acc[k] + bias[c];
            g_x[(size_t)n * HC + c] = v > 0.f ? v : 0.f;
        }
    }
}

// ---------------- global mean pool (batch sorted -> segment reduce) ----------
__global__ void k_pool_seg(const int* __restrict__ batch) {
    int g = blockIdx.x;
    int t = threadIdx.x;
    int lo = 0, hi = N_NODES;
    while (lo < hi) { int m = (lo + hi) >> 1; if (batch[m] < g) lo = m + 1; else hi = m; }
    int beg = lo;
    hi = N_NODES;
    while (lo < hi) { int m = (lo + hi) >> 1; if (batch[m] < g + 1) lo = m + 1; else hi = m; }
    int end = lo;
    float inv = 1.f / fmaxf((float)(end - beg), 1.f);
    for (int c = t; c < HC; c += blockDim.x) {
        float s = 0.f;
        for (int n = beg; n < end; n++) s += g_x[(size_t)n * HC + c];
        g_pool[g * HC + c] = s * inv;
    }
}

// ---------------- fused MLP head ---------------------------------------------
__global__ void k_mlp(const float* __restrict__ lw1, const float* __restrict__ lb1,
                      const float* __restrict__ lw2, const float* __restrict__ lb2,
                      const float* __restrict__ lw3, const float* __restrict__ lb3,
                      float* __restrict__ out) {
    int g = blockIdx.x;
    int t = threadIdx.x;
    __shared__ float buf[HC];
    __shared__ float t1[100];
    __shared__ float t2[100];
    for (int k = t; k < HC; k += blockDim.x) buf[k] = g_pool[g * HC + k];
    __syncthreads();
    if (t < 100) {
        float s = lb1[t];
        for (int k = 0; k < HC; k++) s += buf[k] * lw1[k * 100 + t];
        t1[t] = fmaxf(s, 0.f);
    }
    __syncthreads();
    if (t < 100) {
        float s = lb2[t];
        for (int k = 0; k < 100; k++) s += t1[k] * lw2[k * 100 + t];
        t2[t] = fmaxf(s, 0.f);
    }
    __syncthreads();
    if (t < 29) {
        float s = lb3[t];
        for (int k = 0; k < 100; k++) s += t2[k] * lw3[k * 29 + t];
        out[g * 29 + t] = s;
    }
}

// ---------------- launch ------------------------------------------------------
extern "C" void kernel_launch(void* const* d_in, const int* in_sizes, int n_in,
                              void* d_out, int out_size) {
    const float* x     = (const float*)d_in[0];
    const int*   ei    = (const int*)d_in[1];
    const int*   batch = (const int*)d_in[2];
    const float* W[5];
    const float* Asr[5];
    const float* Ads[5];
    const float* Bc[5];
    for (int i = 0; i < 5; i++) {
        W[i]   = (const float*)d_in[3 + 4 * i];
        Asr[i] = (const float*)d_in[4 + 4 * i];
        Ads[i] = (const float*)d_in[5 + 4 * i];
        Bc[i]  = (const float*)d_in[6 + 4 * i];
    }
    const float* lw1 = (const float*)d_in[23];
    const float* lb1 = (const float*)d_in[24];
    const float* lw2 = (const float*)d_in[25];
    const float* lb2 = (const float*)d_in[26];
    const float* lw3 = (const float*)d_in[27];
    const float* lb3 = (const float*)d_in[28];
    float* out = (float*)d_out;

    k_init_counts<<<(N_NODES + 255) / 256, 256>>>();
    k_count<<<(N_EDGES + 255) / 256, 256>>>(ei);
    k_scan1<<<NB_SCAN, 256>>>();
    k_scan2<<<1, 256>>>();
    k_scan3<<<(N_NODES + 255) / 256, 256>>>();
    k_selfloop<<<(N_NODES + 255) / 256, 256>>>();
    k_fill<<<(N_EDGES + 255) / 256, 256>>>(ei);

    int Kdims[5] = {336, 200, 200, 200, 200};
    int wblocks = (N_NODES + 7) / 8;
    dim3 gemmGrid(2, (TM_TILES + 3) / 4);

    for (int L = 0; L < 5; L++) {
        int K = Kdims[L];
        int KS = (K + 15) / 16;
        int totA = TM_TILES * KS * 32;
        int totB = TN_TILES * KS * 32;
        if (L == 0) k_convA<<<(totA + 255) / 256, 256>>>(x, K, KS, totA);
        else        k_convA_gx<<<(totA + 255) / 256, 256>>>(K, KS, totA);
        k_convB<<<(totB + 255) / 256, 256>>>(W[L], K, KS, totB);
        k_zero_scores<<<(N_NODES * 2 + 255) / 256, 256>>>();
        k_gemm_tc<<<gemmGrid, 256>>>(KS, Asr[L], Ads[L]);
        k_aggregate<<<wblocks, 256>>>(Bc[L]);
    }
    k_pool_seg<<<G_GRAPHS, 256>>>(batch);
    k_mlp<<<G_GRAPHS, 128>>>(lw1, lb1, lw2, lb2, lw3, lb3, out);
}

// round 6
// speedup vs baseline: 1.2089x; 1.2089x over previous
#include <cuda_runtime.h>
#include <cuda_bf16.h>
#include <cstdint>

#define N_NODES 50000
#define N_EDGES 400000
#define E_TOT   (N_EDGES + N_NODES)
#define G_GRAPHS 256
#define HC 200
#define C_CH 100
#define SLOPE 0.2f

#define TM_TILES 3125          // 50000 / 16 (exact)
#define TN_TILES 25            // 200 / 8 (exact)
#define KS16_MAX 21            // 336 / 16
#define NB_SCAN 196            // ceil(50000/256)

// ---------------- scratch (device globals; no allocation allowed) ------------
__device__ float g_h[(size_t)N_NODES * HC];
__device__ float g_x[(size_t)N_NODES * HC];
__device__ float g_es[N_NODES * 2];
__device__ float g_ed[N_NODES * 2];
__device__ float g_alpha[(size_t)E_TOT * 2];
__device__ int   g_rowptr[N_NODES + 1];
__device__ int   g_cnt[N_NODES];
__device__ int   g_fill[N_NODES];
__device__ int   g_colsrc[E_TOT];
__device__ float g_pool[G_GRAPHS * HC];
__device__ int   g_bsum[256];
__device__ int   g_boff[256];
// permuted bf16 hi/lo operands in exact mma.m16n8k16 fragment order
__device__ uint4 g_pah[(size_t)TM_TILES * KS16_MAX * 32];
__device__ uint4 g_pal[(size_t)TM_TILES * KS16_MAX * 32];
__device__ uint2 g_pbh[(size_t)TN_TILES * KS16_MAX * 32];
__device__ uint2 g_pbl[(size_t)TN_TILES * KS16_MAX * 32];

// ---------------- CSR build --------------------------------------------------
__global__ void k_init_counts() {
    int i = blockIdx.x * blockDim.x + threadIdx.x;
    if (i < N_NODES) { g_cnt[i] = 1; g_fill[i] = 1; }
}

__global__ void k_count(const int* __restrict__ ei) {
    int e = blockIdx.x * blockDim.x + threadIdx.x;
    if (e < N_EDGES) atomicAdd(&g_cnt[ei[N_EDGES + e]], 1);
}

__global__ void k_scan1() {
    __shared__ int ws[8];
    int b = blockIdx.x, t = threadIdx.x;
    int i = b * 256 + t;
    int lane = t & 31, w = t >> 5;
    int v = (i < N_NODES) ? g_cnt[i] : 0;
    int s = v;
#pragma unroll
    for (int off = 1; off < 32; off <<= 1) {
        int u = __shfl_up_sync(0xffffffffu, s, off);
        if (lane >= off) s += u;
    }
    if (lane == 31) ws[w] = s;
    __syncthreads();
    if (t == 0) {
        int run = 0;
#pragma unroll
        for (int j = 0; j < 8; j++) { int tmp = ws[j]; ws[j] = run; run += tmp; }
        g_bsum[b] = run;
    }
    __syncthreads();
    if (i < N_NODES) g_rowptr[i + 1] = s + ws[w];
}

__global__ void k_scan2() {
    __shared__ int ws[8];
    int t = threadIdx.x;
    int lane = t & 31, w = t >> 5;
    int v = (t < NB_SCAN) ? g_bsum[t] : 0;
    int s = v;
#pragma unroll
    for (int off = 1; off < 32; off <<= 1) {
        int u = __shfl_up_sync(0xffffffffu, s, off);
        if (lane >= off) s += u;
    }
    if (lane == 31) ws[w] = s;
    __syncthreads();
    if (t == 0) {
        int run = 0;
#pragma unroll
        for (int j = 0; j < 8; j++) { int tmp = ws[j]; ws[j] = run; run += tmp; }
    }
    __syncthreads();
    if (t < NB_SCAN) g_boff[t] = s + ws[w] - v;
}

__global__ void k_scan3() {
    int i = blockIdx.x * blockDim.x + threadIdx.x;
    if (i == 0) g_rowptr[0] = 0;
    if (i < N_NODES) g_rowptr[i + 1] += g_boff[i >> 8];
}

__global__ void k_selfloop() {
    int i = blockIdx.x * blockDim.x + threadIdx.x;
    if (i < N_NODES) g_colsrc[g_rowptr[i]] = i;
}

__global__ void k_fill(const int* __restrict__ ei) {
    int e = blockIdx.x * blockDim.x + threadIdx.x;
    if (e < N_EDGES) {
        int d = ei[N_EDGES + e];
        int pos = g_rowptr[d] + atomicAdd(&g_fill[d], 1);
        g_colsrc[pos] = ei[e];
    }
}

// ---------------- bf16 helpers -----------------------------------------------
__device__ __forceinline__ uint32_t packbf(float a, float b) {
    __nv_bfloat162 p = __floats2bfloat162_rn(a, b);
    return *(uint32_t*)&p;
}
__device__ __forceinline__ float bfhi(float v) {
    return __bfloat162float(__float2bfloat16_rn(v));
}

__device__ __forceinline__ void mma_bf16(float& c0, float& c1, float& c2, float& c3,
                                         uint32_t a0, uint32_t a1, uint32_t a2, uint32_t a3,
                                         uint32_t b0, uint32_t b1) {
    asm volatile(
        "mma.sync.aligned.m16n8k16.row.col.f32.bf16.bf16.f32 "
        "{%0,%1,%2,%3},{%4,%5,%6,%7},{%8,%9},{%0,%1,%2,%3};"
        : "+f"(c0), "+f"(c1), "+f"(c2), "+f"(c3)
        : "r"(a0), "r"(a1), "r"(a2), "r"(a3), "r"(b0), "r"(b1));
}

// ---------------- operand pre-permute + hi/lo bf16 split ---------------------
__device__ __forceinline__ void convA_body(const float* __restrict__ A, int K, int KS, int t) {
    int lane = t & 31;
    int rest = t >> 5;
    int ks = rest % KS;
    int tm = rest / KS;
    int groupr = lane >> 2, kc = lane & 3;
    int r0 = tm * 16 + groupr, r1 = r0 + 8;
    int k0 = ks * 16 + kc * 2;
    float v[2][4];
    const float* p0 = A + (size_t)r0 * K;
    const float* p1 = A + (size_t)r1 * K;
#pragma unroll
    for (int j = 0; j < 4; j++) {
        int k = k0 + (j >> 1) * 8 + (j & 1);
        v[0][j] = (k < K) ? p0[k] : 0.f;
        v[1][j] = (k < K) ? p1[k] : 0.f;
    }
    float h[2][4], l[2][4];
#pragma unroll
    for (int r = 0; r < 2; r++)
#pragma unroll
        for (int j = 0; j < 4; j++) { h[r][j] = bfhi(v[r][j]); l[r][j] = v[r][j] - h[r][j]; }
    g_pah[t] = make_uint4(packbf(h[0][0], h[0][1]), packbf(h[1][0], h[1][1]),
                          packbf(h[0][2], h[0][3]), packbf(h[1][2], h[1][3]));
    g_pal[t] = make_uint4(packbf(l[0][0], l[0][1]), packbf(l[1][0], l[1][1]),
                          packbf(l[0][2], l[0][3]), packbf(l[1][2], l[1][3]));
}

__global__ void k_convA(const float* __restrict__ A, int K, int KS, int total) {
    int t = blockIdx.x * blockDim.x + threadIdx.x;
    if (t < total) convA_body(A, K, KS, t);
}
__global__ void k_convA_gx(int K, int KS, int total) {
    int t = blockIdx.x * blockDim.x + threadIdx.x;
    if (t < total) convA_body(g_x, K, KS, t);
}

__global__ void k_convB(const float* __restrict__ B, int K, int KS, int total) {
    int t = blockIdx.x * blockDim.x + threadIdx.x;
    if (t >= total) return;
    int lane = t & 31;
    int rest = t >> 5;
    int ks = rest % KS;
    int tn = rest / KS;
    int groupr = lane >> 2, kc = lane & 3;
    int n = tn * 8 + groupr;
    int k0 = ks * 16 + kc * 2;
    float v[4];
#pragma unroll
    for (int j = 0; j < 4; j++) {
        int k = k0 + (j >> 1) * 8 + (j & 1);
        v[j] = (k < K) ? B[(size_t)k * HC + n] : 0.f;
    }
    float h[4], l[4];
#pragma unroll
    for (int j = 0; j < 4; j++) { h[j] = bfhi(v[j]); l[j] = v[j] - h[j]; }
    g_pbh[t] = make_uint2(packbf(h[0], h[1]), packbf(h[2], h[3]));
    g_pbl[t] = make_uint2(packbf(l[0], l[1]), packbf(l[2], l[3]));
}

// ---------------- smem-free bf16x3 tensor-core GEMM (round-4 config) ---------
// block = 8 warps (4m x 2n), warp tile 32m x 32n -> 2x4 m16n8k16 tiles.
__global__ void __launch_bounds__(256)
k_gemm_tc(int KS) {
    int tid = threadIdx.x;
    int lane = tid & 31, warp = tid >> 5;
    int wm = warp & 3, wn = warp >> 2;
    int tm0 = blockIdx.y * 8 + wm * 2;
    int tnB = blockIdx.x * 8 + wn * 4;
    if (tnB >= TN_TILES) return;

    bool mv0 = tm0 < TM_TILES;
    bool mv1 = (tm0 + 1) < TM_TILES;
    bool nv[4];
#pragma unroll
    for (int ni = 0; ni < 4; ni++) nv[ni] = (tnB + ni) < TN_TILES;

    size_t aBase0 = ((size_t)tm0 * KS) * 32 + lane;
    size_t aBase1 = aBase0 + (size_t)KS * 32;
    size_t bBase[4];
#pragma unroll
    for (int ni = 0; ni < 4; ni++) bBase[ni] = ((size_t)(tnB + ni) * KS) * 32 + lane;

    float acc[2][4][4];
#pragma unroll
    for (int mi = 0; mi < 2; mi++)
#pragma unroll
        for (int ni = 0; ni < 4; ni++)
#pragma unroll
            for (int r = 0; r < 4; r++) acc[mi][ni][r] = 0.f;

    const uint4 z4 = make_uint4(0, 0, 0, 0);
    const uint2 z2 = make_uint2(0, 0);

#pragma unroll 2
    for (int ks = 0; ks < KS; ks++) {
        size_t off = (size_t)ks * 32;
        uint4 ah0 = mv0 ? g_pah[aBase0 + off] : z4;
        uint4 al0 = mv0 ? g_pal[aBase0 + off] : z4;
        uint4 ah1 = mv1 ? g_pah[aBase1 + off] : z4;
        uint4 al1 = mv1 ? g_pal[aBase1 + off] : z4;
        uint2 bh[4], bl[4];
#pragma unroll
        for (int ni = 0; ni < 4; ni++) {
            bh[ni] = nv[ni] ? g_pbh[bBase[ni] + off] : z2;
            bl[ni] = nv[ni] ? g_pbl[bBase[ni] + off] : z2;
        }
#pragma unroll
        for (int ni = 0; ni < 4; ni++) {
            {
                float* c = acc[0][ni];
                mma_bf16(c[0], c[1], c[2], c[3], ah0.x, ah0.y, ah0.z, ah0.w, bh[ni].x, bh[ni].y);
                mma_bf16(c[0], c[1], c[2], c[3], al0.x, al0.y, al0.z, al0.w, bh[ni].x, bh[ni].y);
                mma_bf16(c[0], c[1], c[2], c[3], ah0.x, ah0.y, ah0.z, ah0.w, bl[ni].x, bl[ni].y);
            }
            {
                float* c = acc[1][ni];
                mma_bf16(c[0], c[1], c[2], c[3], ah1.x, ah1.y, ah1.z, ah1.w, bh[ni].x, bh[ni].y);
                mma_bf16(c[0], c[1], c[2], c[3], al1.x, al1.y, al1.z, al1.w, bh[ni].x, bh[ni].y);
                mma_bf16(c[0], c[1], c[2], c[3], ah1.x, ah1.y, ah1.z, ah1.w, bl[ni].x, bl[ni].y);
            }
        }
    }

    int groupr = lane >> 2, kc = lane & 3;
#pragma unroll
    for (int mi = 0; mi < 2; mi++) {
        if (!(mi ? mv1 : mv0)) continue;
        int r = (tm0 + mi) * 16 + groupr;
#pragma unroll
        for (int ni = 0; ni < 4; ni++) {
            if (!nv[ni]) continue;
            int c = (tnB + ni) * 8 + kc * 2;
            g_h[(size_t)r * HC + c]           = acc[mi][ni][0];
            g_h[(size_t)r * HC + c + 1]       = acc[mi][ni][1];
            g_h[(size_t)(r + 8) * HC + c]     = acc[mi][ni][2];
            g_h[(size_t)(r + 8) * HC + c + 1] = acc[mi][ni][3];
        }
    }
}

// ---------------- per-node attention scores ----------------------------------
__global__ void k_scores(const float* __restrict__ a_s, const float* __restrict__ a_d) {
    int gwarp = (blockIdx.x * blockDim.x + threadIdx.x) >> 5;
    int lane = threadIdx.x & 31;
    if (gwarp >= N_NODES) return;
    const float* hr = g_h + (size_t)gwarp * HC;
    float s0s = 0.f, s1s = 0.f, s0d = 0.f, s1d = 0.f;
#pragma unroll
    for (int k = 0; k < 7; k++) {
        int c = lane + 32 * k;
        if (c < HC) {
            float v = hr[c];
            float vs = v * a_s[c], vd = v * a_d[c];
            if (c < C_CH) { s0s += vs; s0d += vd; }
            else          { s1s += vs; s1d += vd; }
        }
    }
#pragma unroll
    for (int off = 16; off; off >>= 1) {
        s0s += __shfl_xor_sync(0xffffffffu, s0s, off);
        s1s += __shfl_xor_sync(0xffffffffu, s1s, off);
        s0d += __shfl_xor_sync(0xffffffffu, s0d, off);
        s1d += __shfl_xor_sync(0xffffffffu, s1d, off);
    }
    if (lane == 0) {
        g_es[gwarp * 2 + 0] = s0s; g_es[gwarp * 2 + 1] = s1s;
        g_ed[gwarp * 2 + 0] = s0d; g_ed[gwarp * 2 + 1] = s1d;
    }
}

__device__ __forceinline__ float lrelu(float v) { return v >= 0.f ? v : SLOPE * v; }

// ---------------- warp-per-dst softmax + aggregate + bias + relu -------------
// exp computed ONCE per edge (sum pass, stored to g_alpha), reused in the
// weighted pass as a broadcast load -> kills the 32x-redundant MUFU work.
__global__ void k_aggregate(const float* __restrict__ bias) {
    int n = (blockIdx.x * blockDim.x + threadIdx.x) >> 5;
    int lane = threadIdx.x & 31;
    if (n >= N_NODES) return;
    int beg = g_rowptr[n], end = g_rowptr[n + 1];
    float ed0 = g_ed[n * 2 + 0], ed1 = g_ed[n * 2 + 1];

    float m0 = -1e30f, m1 = -1e30f;
    for (int i = beg + lane; i < end; i += 32) {
        int s = g_colsrc[i];
        m0 = fmaxf(m0, lrelu(g_es[s * 2 + 0] + ed0));
        m1 = fmaxf(m1, lrelu(g_es[s * 2 + 1] + ed1));
    }
#pragma unroll
    for (int off = 16; off; off >>= 1) {
        m0 = fmaxf(m0, __shfl_xor_sync(0xffffffffu, m0, off));
        m1 = fmaxf(m1, __shfl_xor_sync(0xffffffffu, m1, off));
    }

    float s0 = 0.f, s1 = 0.f;
    for (int i = beg + lane; i < end; i += 32) {
        int s = g_colsrc[i];
        float p0 = __expf(lrelu(g_es[s * 2 + 0] + ed0) - m0);
        float p1 = __expf(lrelu(g_es[s * 2 + 1] + ed1) - m1);
        ((float2*)g_alpha)[i] = make_float2(p0, p1);
        s0 += p0;
        s1 += p1;
    }
    __threadfence_block();    // make g_alpha writes visible warp/block-wide
#pragma unroll
    for (int off = 16; off; off >>= 1) {
        s0 += __shfl_xor_sync(0xffffffffu, s0, off);
        s1 += __shfl_xor_sync(0xffffffffu, s1, off);
    }
    float inv0 = 1.f / (s0 + 1e-16f), inv1 = 1.f / (s1 + 1e-16f);

    float acc[7];
#pragma unroll
    for (int k = 0; k < 7; k++) acc[k] = 0.f;

    for (int i = beg; i < end; i++) {
        int s = g_colsrc[i];
        float2 p = ((const float2*)g_alpha)[i];   // broadcast load
        float a0 = p.x * inv0;
        float a1 = p.y * inv1;
        const float* hr = g_h + (size_t)s * HC;
#pragma unroll
        for (int k = 0; k < 7; k++) {
            int c = lane + 32 * k;
            if (c < HC) acc[k] += (c < C_CH ? a0 : a1) * hr[c];
        }
    }
#pragma unroll
    for (int k = 0; k < 7; k++) {
        int c = lane + 32 * k;
        if (c < HC) {
            float v = acc[k] + bias[c];
            g_x[(size_t)n * HC + c] = v > 0.f ? v : 0.f;
        }
    }
}

// ---------------- global mean pool (batch sorted -> segment reduce) ----------
__global__ void k_pool_seg(const int* __restrict__ batch) {
    int g = blockIdx.x;
    int t = threadIdx.x;
    int lo = 0, hi = N_NODES;
    while (lo < hi) { int m = (lo + hi) >> 1; if (batch[m] < g) lo = m + 1; else hi = m; }
    int beg = lo;
    hi = N_NODES;
    while (lo < hi) { int m = (lo + hi) >> 1; if (batch[m] < g + 1) lo = m + 1; else hi = m; }
    int end = lo;
    float inv = 1.f / fmaxf((float)(end - beg), 1.f);
    for (int c = t; c < HC; c += blockDim.x) {
        float s = 0.f;
        for (int n = beg; n < end; n++) s += g_x[(size_t)n * HC + c];
        g_pool[g * HC + c] = s * inv;
    }
}

// ---------------- fused MLP head ---------------------------------------------
__global__ void k_mlp(const float* __restrict__ lw1, const float* __restrict__ lb1,
                      const float* __restrict__ lw2, const float* __restrict__ lb2,
                      const float* __restrict__ lw3, const float* __restrict__ lb3,
                      float* __restrict__ out) {
    int g = blockIdx.x;
    int t = threadIdx.x;
    __shared__ float buf[HC];
    __shared__ float t1[100];
    __shared__ float t2[100];
    for (int k = t; k < HC; k += blockDim.x) buf[k] = g_pool[g * HC + k];
    __syncthreads();
    if (t < 100) {
        float s = lb1[t];
        for (int k = 0; k < HC; k++) s += buf[k] * lw1[k * 100 + t];
        t1[t] = fmaxf(s, 0.f);
    }
    __syncthreads();
    if (t < 100) {
        float s = lb2[t];
        for (int k = 0; k < 100; k++) s += t1[k] * lw2[k * 100 + t];
        t2[t] = fmaxf(s, 0.f);
    }
    __syncthreads();
    if (t < 29) {
        float s = lb3[t];
        for (int k = 0; k < 100; k++) s += t2[k] * lw3[k * 29 + t];
        out[g * 29 + t] = s;
    }
}

// ---------------- launch ------------------------------------------------------
extern "C" void kernel_launch(void* const* d_in, const int* in_sizes, int n_in,
                              void* d_out, int out_size) {
    const float* x     = (const float*)d_in[0];
    const int*   ei    = (const int*)d_in[1];
    const int*   batch = (const int*)d_in[2];
    const float* W[5];
    const float* Asr[5];
    const float* Ads[5];
    const float* Bc[5];
    for (int i = 0; i < 5; i++) {
        W[i]   = (const float*)d_in[3 + 4 * i];
        Asr[i] = (const float*)d_in[4 + 4 * i];
        Ads[i] = (const float*)d_in[5 + 4 * i];
        Bc[i]  = (const float*)d_in[6 + 4 * i];
    }
    const float* lw1 = (const float*)d_in[23];
    const float* lb1 = (const float*)d_in[24];
    const float* lw2 = (const float*)d_in[25];
    const float* lb2 = (const float*)d_in[26];
    const float* lw3 = (const float*)d_in[27];
    const float* lb3 = (const float*)d_in[28];
    float* out = (float*)d_out;

    k_init_counts<<<(N_NODES + 255) / 256, 256>>>();
    k_count<<<(N_EDGES + 255) / 256, 256>>>(ei);
    k_scan1<<<NB_SCAN, 256>>>();
    k_scan2<<<1, 256>>>();
    k_scan3<<<(N_NODES + 255) / 256, 256>>>();
    k_selfloop<<<(N_NODES + 255) / 256, 256>>>();
    k_fill<<<(N_EDGES + 255) / 256, 256>>>(ei);

    int Kdims[5] = {336, 200, 200, 200, 200};
    int wblocks = (N_NODES + 7) / 8;
    dim3 gemmGrid(4, (TM_TILES + 7) / 8);

    for (int L = 0; L < 5; L++) {
        int K = Kdims[L];
        int KS = (K + 15) / 16;
        int totA = TM_TILES * KS * 32;
        int totB = TN_TILES * KS * 32;
        if (L == 0) k_convA<<<(totA + 255) / 256, 256>>>(x, K, KS, totA);
        else        k_convA_gx<<<(totA + 255) / 256, 256>>>(K, KS, totA);
        k_convB<<<(totB + 255) / 256, 256>>>(W[L], K, KS, totB);
        k_gemm_tc<<<gemmGrid, 256>>>(KS);
        k_scores<<<wblocks, 256>>>(Asr[L], Ads[L]);
        k_aggregate<<<wblocks, 256>>>(Bc[L]);
    }
    k_pool_seg<<<G_GRAPHS, 256>>>(batch);
    k_mlp<<<G_GRAPHS, 128>>>(lw1, lb1, lw2, lb2, lw3, lb3, out);
}